// round 1
// baseline (speedup 1.0000x reference)
#include <cuda_runtime.h>
#include <cstdint>

#define NROW     256
#define S_STEPS  4001          // hs length (M+1)
#define M_STEPS  4000
#define NCHUNK   148
#define CLEN     28            // 148*28 = 4144 >= 4001
#define GP_SIZE  33152         // sum_i (i+2) for i in [0,255]
#define CODE_UP   300
#define CODE_NONE 301
#define RINF     (1<<20)

// ---- device scratch (no allocations allowed) ----
__device__ __align__(16) float g_Gp[GP_SIZE];   // packed G(i,c), c in [-1..i] at off_i + 1 + c
__device__ float g_R[NROW];                     // row sums of dens
__device__ int   g_sum_r[NCHUNK * NROW];        // chunk summary: per-row forced value (RINF = pass)
__device__ int   g_sum_K[NCHUNK];               // chunk summary: global min-clamp
__device__ int   g_cs[NCHUNK * NROW];           // chunk-entry state c[i]

__device__ __forceinline__ float xval(int i) {
    if (i >= 255) return 1.0f;
    if (i <= 0)   return 0.0f;
    return (float)i * (1.0f / 255.0f);
}

// hs[s]: hs[0] = 1.0 (= -H_MIN normalized), else (h_data[s-1]+1)/2 (bit-identical to ref)
__device__ __forceinline__ float hnorm(const float* __restrict__ hd, int s) {
    return (s == 0) ? 1.0f : (hd[s - 1] + 1.0f) * 0.5f;
}

// classify step s: up (h>p), down (h<p, with jmax), or none
__device__ __forceinline__ void make_step(const float* __restrict__ hd, int s,
                                          float& h, int& code) {
    h = hnorm(hd, s);
    int pi = (s == 0) ? (S_STEPS - 1) : (s - 1);
    float p = hnorm(hd, pi);
    if (h > p) {
        code = CODE_UP;
    } else if (h < p) {
        int jm = (int)(h * 255.0f);
        if (jm > 255) jm = 255;
        if (jm < 0)   jm = 0;
        while (jm < 255 && xval(jm + 1) <= h) ++jm;   // exact float semantics
        while (jm >= 0 && xval(jm) > h)      --jm;
        code = jm;                                    // jmax in [-1, 255]
    } else {
        code = CODE_NONE;
    }
}

// jax.nn.softplus = logaddexp(x,0) = max(x,0) + log1p(exp(-|x|))
__device__ __forceinline__ float softplus_f(float x) {
    return fmaxf(x, 0.0f) + log1pf(expf(-fabsf(x)));
}

// ---- kA: blocks [0,256): build G table; blocks [256,256+NCHUNK): chunk summaries ----
__global__ void kA(const float* __restrict__ raw, const float* __restrict__ hd) {
    int tid = threadIdx.x, ln = tid & 31, w = tid >> 5;

    if (blockIdx.x < NROW) {
        // --- build row i of packed G ---
        int i = blockIdx.x;
        int base = i * (i + 1) / 2;
        float v = (tid <= i) ? softplus_f(raw[base + tid]) : 0.0f;

        // inclusive block scan of v over 256 threads
        float s = v;
        #pragma unroll
        for (int o = 1; o < 32; o <<= 1) {
            float t = __shfl_up_sync(0xffffffffu, s, o);
            if (ln >= o) s += t;
        }
        __shared__ float wtot[8];
        if (ln == 31) wtot[w] = s;
        __syncthreads();
        if (w == 0) {
            float t = (ln < 8) ? wtot[ln] : 0.0f;
            #pragma unroll
            for (int o = 1; o < 8; o <<= 1) {
                float u = __shfl_up_sync(0xffffffffu, t, o);
                if (ln >= o) t += u;
            }
            if (ln < 8) wtot[ln] = t;
        }
        __syncthreads();
        float pre = s + ((w > 0) ? wtot[w - 1] : 0.0f);
        float R = wtot[7];  // total row sum (v=0 beyond row length)

        int off = i * (i + 3) / 2;
        if (tid <= i) g_Gp[off + 1 + tid] = 2.0f * pre - R;
        if (tid == 0) { g_Gp[off] = -R; g_R[i] = R; }
    } else {
        // --- summarize chunk k ---
        int k = blockIdx.x - NROW;
        __shared__ float sh[CLEN];
        __shared__ int   sc[CLEN];
        if (tid < CLEN) {
            int s = k * CLEN + tid;
            float h = 0.0f; int code = CODE_NONE;
            if (s < S_STEPS) make_step(hd, s, h, code);
            sh[tid] = h; sc[tid] = code;
        }
        __syncthreads();

        int i = tid;
        float xi = xval(i);
        int r = RINF, K = RINF;
        #pragma unroll
        for (int l = 0; l < CLEN; l++) {
            int cd = sc[l];
            if (cd == CODE_UP) {
                if (xi < sh[l]) r = i;             // force full row
            } else if (cd != CODE_NONE) {
                if (r != RINF) r = min(r, cd);     // clamp forced value
                K = min(K, cd);                    // clamp pass-through
            }
        }
        g_sum_r[k * NROW + i] = r;
        if (tid == 0) g_sum_K[k] = K;
    }
}

// ---- kB: compose summaries sequentially -> chunk-entry states ----
__global__ void kB() {
    int i = threadIdx.x;
    int c = -1;                    // initial Preisach state (all -1)
    int r = g_sum_r[i];
    for (int k = 0; k < NCHUNK; k++) {
        int rn = (k + 1 < NCHUNK) ? g_sum_r[(k + 1) * NROW + i] : 0;  // prefetch
        int K  = g_sum_K[k];
        g_cs[k * NROW + i] = c;
        c = (r != RINF) ? r : min(c, K);
        r = rn;
    }
}

// ---- kC: replay each chunk with shared-memory G, emit b[t] per step ----
extern __shared__ float shG[];   // GP_SIZE floats
__global__ void kC(const float* __restrict__ hd, float* __restrict__ out) {
    int k = blockIdx.x, tid = threadIdx.x, ln = tid & 31, w = tid >> 5;
    __shared__ float sh[CLEN];
    __shared__ int   sc[CLEN];
    __shared__ float wsum[8];
    __shared__ float sa;

    if (tid < CLEN) {
        int s = k * CLEN + tid;
        float h = 0.0f; int code = CODE_NONE;
        if (s < S_STEPS) make_step(hd, s, h, code);
        sh[tid] = h; sc[tid] = code;
    }

    // a = 1 / sum(dens): deterministic block reduction of g_R (identical in every block)
    float v = g_R[tid];
    #pragma unroll
    for (int o = 16; o; o >>= 1) v += __shfl_xor_sync(0xffffffffu, v, o);
    if (ln == 0) wsum[w] = v;
    __syncthreads();
    if (w == 0) {
        float t = (ln < 8) ? wsum[ln] : 0.0f;
        #pragma unroll
        for (int o = 4; o; o >>= 1) t += __shfl_xor_sync(0xffffffffu, t, o);
        if (ln == 0) sa = 1.0f / t;
    }

    // stage G into shared (132.6 KB), 16B vectors
    {
        const float4* src = (const float4*)g_Gp;
        float4* dst = (float4*)shG;
        for (int j = tid; j < GP_SIZE / 4; j += 256) dst[j] = src[j];
    }
    __syncthreads();
    float a = sa;

    int i = tid;
    float xi = xval(i);
    int off = i * (i + 3) / 2;
    int c = g_cs[k * NROW + i];
    float gi = shG[off + 1 + c];

    for (int l = 0; l < CLEN; l++) {
        int s = k * CLEN + l;
        int cd = sc[l];
        int cn = c;
        if (cd == CODE_UP) {
            if (xi < sh[l]) cn = i;
        } else if (cd != CODE_NONE) {
            cn = min(c, cd);
        }
        if (cn != c) { c = cn; gi = shG[off + 1 + c]; }

        // deterministic block reduction of gi -> b[s-1]
        float vv = gi;
        #pragma unroll
        for (int o = 16; o; o >>= 1) vv += __shfl_xor_sync(0xffffffffu, vv, o);
        if (ln == 0) wsum[w] = vv;
        __syncthreads();
        if (w == 0) {
            float t = (ln < 8) ? wsum[ln] : 0.0f;
            #pragma unroll
            for (int o = 4; o; o >>= 1) t += __shfl_xor_sync(0xffffffffu, t, o);
            if (ln == 0 && s >= 1 && s < S_STEPS) out[s - 1] = a * t;
        }
        __syncthreads();
    }
}

extern "C" void kernel_launch(void* const* d_in, const int* in_sizes, int n_in,
                              void* d_out, int out_size) {
    const float* hd  = (const float*)d_in[0];   // h_data (4000)
    const float* raw = (const float*)d_in[1];   // raw density (32896)
    if (n_in >= 2 && in_sizes[0] != M_STEPS) {  // defensive: match by size
        const float* t = hd; hd = raw; raw = t;
    }
    float* out = (float*)d_out;

    cudaFuncSetAttribute(kC, cudaFuncAttributeMaxDynamicSharedMemorySize, GP_SIZE * 4);

    kA<<<NROW + NCHUNK, 256>>>(raw, hd);
    kB<<<1, NROW>>>();
    kC<<<NCHUNK, 256, GP_SIZE * 4>>>(hd, out);
}

// round 3
// speedup vs baseline: 1.8239x; 1.8239x over previous
#include <cuda_runtime.h>
#include <cstdint>

#define NROW     256
#define S_STEPS  4001          // hs length (M+1)
#define M_STEPS  4000
#define NCHUNK   148
#define CLEN     28            // 148*28 = 4144 >= 4001
#define GP_SIZE  33152         // sum_i (i+2) for i in [0,255]
#define CODE_UP   300
#define CODE_NONE 301
#define RINF     (1<<20)

// ---- device scratch (no allocations allowed) ----
__device__ __align__(16) float g_Gp[GP_SIZE];   // packed G(i,c): row i at off=i*(i+3)/2, index off+1+c, c in [-1..i]
__device__ float g_R[NROW];                     // row sums of dens
__device__ int   g_sum_r[NCHUNK * NROW];        // chunk summary: per-row forced value (RINF = pass-through)
__device__ int   g_sum_K[NCHUNK];               // chunk summary: global min-clamp

__device__ __forceinline__ float xval(int i) {
    if (i >= 255) return 1.0f;
    if (i <= 0)   return 0.0f;
    return (float)i * (1.0f / 255.0f);
}

// hs[s]: hs[0] = 1.0 (= -H_MIN normalized), else (h_data[s-1]+1)/2 (bit-identical to ref)
__device__ __forceinline__ float hnorm(const float* __restrict__ hd, int s) {
    return (s == 0) ? 1.0f : (hd[s - 1] + 1.0f) * 0.5f;
}

// classify step s: up (h>p), down (h<p, code=jmax), or none
__device__ __forceinline__ void make_step(const float* __restrict__ hd, int s,
                                          float& h, int& code) {
    h = hnorm(hd, s);
    int pi = (s == 0) ? (S_STEPS - 1) : (s - 1);
    float p = hnorm(hd, pi);
    if (h > p) {
        code = CODE_UP;
    } else if (h < p) {
        int jm = (int)(h * 255.0f);
        if (jm > 255) jm = 255;
        if (jm < 0)   jm = 0;
        while (jm < 255 && xval(jm + 1) <= h) ++jm;   // exact float semantics
        while (jm >= 0 && xval(jm) > h)      --jm;
        code = jm;                                    // jmax in [-1, 255]
    } else {
        code = CODE_NONE;
    }
}

// jax.nn.softplus = max(x,0) + log1p(exp(-|x|))
__device__ __forceinline__ float softplus_f(float x) {
    return fmaxf(x, 0.0f) + log1pf(expf(-fabsf(x)));
}

// ---- kA: grid=148. Block b builds G rows {b, b+148} and chunk-b summary. ----
__global__ void kA(const float* __restrict__ raw, const float* __restrict__ hd) {
    int tid = threadIdx.x, ln = tid & 31, w = tid >> 5;
    __shared__ float wtot[8];

    // --- build up to 2 rows of packed G via 256-wide block scan ---
    #pragma unroll
    for (int rr = 0; rr < 2; rr++) {
        int i = blockIdx.x + rr * NCHUNK;
        if (i < NROW) {
            int base = i * (i + 1) / 2;
            float v = (tid <= i) ? softplus_f(raw[base + tid]) : 0.0f;

            float s = v;
            #pragma unroll
            for (int o = 1; o < 32; o <<= 1) {
                float t = __shfl_up_sync(0xffffffffu, s, o);
                if (ln >= o) s += t;
            }
            if (ln == 31) wtot[w] = s;
            __syncthreads();
            if (w == 0) {
                float t = (ln < 8) ? wtot[ln] : 0.0f;
                #pragma unroll
                for (int o = 1; o < 8; o <<= 1) {
                    float u = __shfl_up_sync(0xffffffffu, t, o);
                    if (ln >= o) t += u;
                }
                if (ln < 8) wtot[ln] = t;
            }
            __syncthreads();
            float pre = s + ((w > 0) ? wtot[w - 1] : 0.0f);
            float R = wtot[7];

            int off = i * (i + 3) / 2;
            if (tid <= i) g_Gp[off + 1 + tid] = 2.0f * pre - R;
            if (tid == 0) { g_Gp[off] = -R; g_R[i] = R; }
            __syncthreads();   // wtot reuse
        }
    }

    // --- summarize chunk k = blockIdx.x ---
    int k = blockIdx.x;
    __shared__ float sh[CLEN];
    __shared__ int   sc[CLEN];
    if (tid < CLEN) {
        int s = k * CLEN + tid;
        float h = 0.0f; int code = CODE_NONE;
        if (s < S_STEPS) make_step(hd, s, h, code);
        sh[tid] = h; sc[tid] = code;
    }
    __syncthreads();

    int i = tid;
    float xi = xval(i);
    int r = RINF, K = RINF;
    #pragma unroll
    for (int l = 0; l < CLEN; l++) {
        int cd = sc[l];
        if (cd == CODE_UP) {
            if (xi < sh[l]) r = i;             // force full row
        } else if (cd != CODE_NONE) {
            if (r != RINF) r = min(r, cd);     // clamp forced value
            K = min(K, cd);                    // clamp pass-through
        }
    }
    g_sum_r[k * NROW + i] = r;
    if (tid == 0) g_sum_K[k] = K;
}

// ---- kC: each block self-composes its entry state, replays its chunk ----
extern __shared__ float shG[];   // GP_SIZE floats (132.6 KB)
__global__ void kC(const float* __restrict__ hd, float* __restrict__ out) {
    int k = blockIdx.x, tid = threadIdx.x, ln = tid & 31, w = tid >> 5;
    __shared__ float sh[CLEN];
    __shared__ int   sc[CLEN];
    __shared__ int   shK[NCHUNK];
    __shared__ float wsum[8];
    __shared__ float sa;
    __shared__ float mat[CLEN * NROW];   // gi per (step, row)

    // step descriptors for this chunk
    if (tid < CLEN) {
        int s = k * CLEN + tid;
        float h = 0.0f; int code = CODE_NONE;
        if (s < S_STEPS) make_step(hd, s, h, code);
        sh[tid] = h; sc[tid] = code;
    }
    if (tid < NCHUNK) shK[tid] = g_sum_K[tid];

    // a = 1/sum(dens): deterministic block reduction (identical in every block)
    float v = g_R[tid];
    #pragma unroll
    for (int o = 16; o; o >>= 1) v += __shfl_xor_sync(0xffffffffu, v, o);
    if (ln == 0) wsum[w] = v;
    __syncthreads();
    if (w == 0) {
        float t = (ln < 8) ? wsum[ln] : 0.0f;
        #pragma unroll
        for (int o = 4; o; o >>= 1) t += __shfl_xor_sync(0xffffffffu, t, o);
        if (ln == 0) sa = 1.0f / t;
    }

    // self-compose entry state from chunk summaries 0..k-1 (MLP-friendly: only
    // the cheap ALU combine is loop-carried; all load addresses independent)
    int c = -1;
    {
        int kk = 0;
        const int* rr = g_sum_r + tid;
        for (; kk + 4 <= k; kk += 4) {
            int r0 = rr[(kk + 0) * NROW];
            int r1 = rr[(kk + 1) * NROW];
            int r2 = rr[(kk + 2) * NROW];
            int r3 = rr[(kk + 3) * NROW];
            c = (r0 != RINF) ? r0 : min(c, shK[kk + 0]);
            c = (r1 != RINF) ? r1 : min(c, shK[kk + 1]);
            c = (r2 != RINF) ? r2 : min(c, shK[kk + 2]);
            c = (r3 != RINF) ? r3 : min(c, shK[kk + 3]);
        }
        for (; kk < k; kk++) {
            int r0 = rr[kk * NROW];
            c = (r0 != RINF) ? r0 : min(c, shK[kk]);
        }
    }

    // stage G into dynamic shared (132.6 KB), 16B vectors
    {
        const float4* src = (const float4*)g_Gp;
        float4* dst = (float4*)shG;
        for (int j = tid; j < GP_SIZE / 4; j += 256) dst[j] = src[j];
    }
    __syncthreads();
    float a = sa;

    // replay: each thread owns row i, writes gi per step into mat (no syncs)
    int i = tid;
    float xi = xval(i);
    int off = i * (i + 3) / 2;
    float gi = shG[off + 1 + c];
    #pragma unroll
    for (int l = 0; l < CLEN; l++) {
        int cd = sc[l];
        int cn = c;
        if (cd == CODE_UP) {
            if (xi < sh[l]) cn = i;
        } else if (cd != CODE_NONE) {
            cn = min(c, cd);
        }
        if (cn != c) { c = cn; gi = shG[off + 1 + c]; }
        mat[l * NROW + i] = gi;
    }
    __syncthreads();

    // barrier-free epilogue: warp w reduces steps l = w, w+8, ...
    for (int l = w; l < CLEN; l += 8) {
        int s = k * CLEN + l;
        const float* row = mat + l * NROW;
        float t = 0.0f;
        #pragma unroll
        for (int j = 0; j < 8; j++) t += row[ln + 32 * j];
        #pragma unroll
        for (int o = 16; o; o >>= 1) t += __shfl_xor_sync(0xffffffffu, t, o);
        if (ln == 0 && s >= 1 && s < S_STEPS) out[s - 1] = a * t;
    }
}

extern "C" void kernel_launch(void* const* d_in, const int* in_sizes, int n_in,
                              void* d_out, int out_size) {
    const float* hd  = (const float*)d_in[0];   // h_data (4000)
    const float* raw = (const float*)d_in[1];   // raw density (32896)
    if (n_in >= 2 && in_sizes[0] != M_STEPS) {  // defensive: match by size
        const float* t = hd; hd = raw; raw = t;
    }
    float* out = (float*)d_out;

    cudaFuncSetAttribute(kC, cudaFuncAttributeMaxDynamicSharedMemorySize, GP_SIZE * 4);

    kA<<<NCHUNK, 256>>>(raw, hd);
    kC<<<NCHUNK, 256, GP_SIZE * 4>>>(hd, out);
}

// round 4
// speedup vs baseline: 1.8547x; 1.0169x over previous
#include <cuda_runtime.h>
#include <cstdint>

#define NROW     256
#define S_STEPS  4001          // hs length (M+1)
#define M_STEPS  4000
#define NCHUNK   148
#define CLEN     28            // 148*28 = 4144 >= 4001
#define GP_SIZE  33152         // sum_i (i+2) for i in [0,255]
#define GP_BYTES (GP_SIZE * 4) // 132608, multiple of 16
#define CODE_UP   300
#define CODE_NONE 301
#define RINF     (1<<20)
#define GSZ      16            // chunks per summary group
#define NGRP     10            // ceil(148/16)

// ---- device scratch (no allocations allowed) ----
__device__ __align__(16) float g_Gp[GP_SIZE];   // packed G(i,c): row i at off=i*(i+3)/2, index off+1+c
__device__ float g_R[NROW];                     // row sums of dens
__device__ int   g_sum_r[NCHUNK * NROW];        // per-chunk transform: forced value (RINF = pass)
__device__ int   g_sum_K[NCHUNK];               // per-chunk transform: min-clamp
__device__ int   g_grp_r[NGRP * NROW];          // group-composed transforms
__device__ int   g_grp_K[NGRP];

__device__ __forceinline__ float xval(int i) {
    if (i >= 255) return 1.0f;
    if (i <= 0)   return 0.0f;
    return (float)i * (1.0f / 255.0f);
}

__device__ __forceinline__ float hnorm(const float* __restrict__ hd, int s) {
    return (s == 0) ? 1.0f : (hd[s - 1] + 1.0f) * 0.5f;
}

// classify step s: up (h>p), down (h<p, code=jmax), or none
__device__ __forceinline__ void make_step(const float* __restrict__ hd, int s,
                                          float& h, int& code) {
    h = hnorm(hd, s);
    int pi = (s == 0) ? (S_STEPS - 1) : (s - 1);
    float p = hnorm(hd, pi);
    if (h > p) {
        code = CODE_UP;
    } else if (h < p) {
        int jm = (int)(h * 255.0f);
        if (jm > 255) jm = 255;
        if (jm < 0)   jm = 0;
        while (jm < 255 && xval(jm + 1) <= h) ++jm;   // exact float semantics
        while (jm >= 0 && xval(jm) > h)      --jm;
        code = jm;                                    // jmax in [-1, 255]
    } else {
        code = CODE_NONE;
    }
}

// jax.nn.softplus = max(x,0) + log1p(exp(-|x|))
__device__ __forceinline__ float softplus_f(float x) {
    return fmaxf(x, 0.0f) + log1pf(expf(-fabsf(x)));
}

__device__ __forceinline__ uint32_t s2u(const void* p) {
    uint32_t a;
    asm("{ .reg .u64 t; cvta.to.shared.u64 t, %1; cvt.u32.u64 %0, t; }" : "=r"(a) : "l"(p));
    return a;
}

// ---- kA: grid=148. Block b builds G rows {b, b+148} and chunk-b summary. ----
__global__ void kA(const float* __restrict__ raw, const float* __restrict__ hd) {
    int tid = threadIdx.x, ln = tid & 31, w = tid >> 5;
    __shared__ float wtot[8];

    #pragma unroll
    for (int rr = 0; rr < 2; rr++) {
        int i = blockIdx.x + rr * NCHUNK;
        if (i < NROW) {
            int base = i * (i + 1) / 2;
            float v = (tid <= i) ? softplus_f(raw[base + tid]) : 0.0f;

            float s = v;
            #pragma unroll
            for (int o = 1; o < 32; o <<= 1) {
                float t = __shfl_up_sync(0xffffffffu, s, o);
                if (ln >= o) s += t;
            }
            if (ln == 31) wtot[w] = s;
            __syncthreads();
            if (w == 0) {
                float t = (ln < 8) ? wtot[ln] : 0.0f;
                #pragma unroll
                for (int o = 1; o < 8; o <<= 1) {
                    float u = __shfl_up_sync(0xffffffffu, t, o);
                    if (ln >= o) t += u;
                }
                if (ln < 8) wtot[ln] = t;
            }
            __syncthreads();
            float pre = s + ((w > 0) ? wtot[w - 1] : 0.0f);
            float R = wtot[7];

            int off = i * (i + 3) / 2;
            if (tid <= i) g_Gp[off + 1 + tid] = 2.0f * pre - R;
            if (tid == 0) { g_Gp[off] = -R; g_R[i] = R; }
            __syncthreads();   // wtot reuse
        }
    }

    // --- summarize chunk k = blockIdx.x ---
    int k = blockIdx.x;
    __shared__ float sh[CLEN];
    __shared__ int   sc[CLEN];
    if (tid < CLEN) {
        int s = k * CLEN + tid;
        float h = 0.0f; int code = CODE_NONE;
        if (s < S_STEPS) make_step(hd, s, h, code);
        sh[tid] = h; sc[tid] = code;
    }
    __syncthreads();

    int i = tid;
    float xi = xval(i);
    int r = RINF, K = RINF;
    #pragma unroll
    for (int l = 0; l < CLEN; l++) {
        int cd = sc[l];
        if (cd == CODE_UP) {
            if (xi < sh[l]) r = i;
        } else if (cd != CODE_NONE) {
            if (r != RINF) r = min(r, cd);
            K = min(K, cd);
        }
    }
    g_sum_r[k * NROW + i] = r;
    if (tid == 0) g_sum_K[k] = K;
}

// ---- kB: compose each group of 16 chunk transforms (associative) ----
__global__ void kB() {
    int g = blockIdx.x, i = threadIdx.x;
    int lo = g * GSZ, hi = min(lo + GSZ, NCHUNK);
    int R = RINF, K = RINF;   // identity transform
    #pragma unroll 4
    for (int c = lo; c < hi; c++) {
        int r  = g_sum_r[c * NROW + i];
        int Kc = g_sum_K[c];
        R = (r != RINF) ? r : ((R != RINF) ? min(R, Kc) : RINF);
        K = min(K, Kc);
    }
    g_grp_r[g * NROW + i] = R;
    if (i == 0) g_grp_K[g] = K;
}

// ---- kC: bulk-copy G to smem (async), compose entry state, replay chunk ----
extern __shared__ float shG[];   // GP_SIZE floats (132.6 KB)
__global__ void kC(const float* __restrict__ hd, float* __restrict__ out) {
    int k = blockIdx.x, tid = threadIdx.x, ln = tid & 31, w = tid >> 5;
    __shared__ float sh[CLEN];
    __shared__ int   sc[CLEN];
    __shared__ int   shK[NCHUNK];
    __shared__ float wsum[8];
    __shared__ float sa;
    __shared__ float mat[CLEN * NROW];
    __shared__ __align__(8) unsigned long long mbar;

    // init mbarrier, then kick off the 132 KB bulk global->shared copy
    uint32_t mb = s2u(&mbar);
    if (tid == 0) {
        asm volatile("mbarrier.init.shared.b64 [%0], 1;" :: "r"(mb) : "memory");
    }
    __syncthreads();
    if (tid == 0) {
        asm volatile("mbarrier.arrive.expect_tx.shared.b64 _, [%0], %1;"
                     :: "r"(mb), "r"((uint32_t)GP_BYTES) : "memory");
        asm volatile("cp.async.bulk.shared::cluster.global.mbarrier::complete_tx::bytes "
                     "[%0], [%1], %2, [%3];"
                     :: "r"(s2u(shG)), "l"((const void*)g_Gp),
                        "r"((uint32_t)GP_BYTES), "r"(mb) : "memory");
    }

    // step descriptors for this chunk (independent of shG)
    if (tid < CLEN) {
        int s = k * CLEN + tid;
        float h = 0.0f; int code = CODE_NONE;
        if (s < S_STEPS) make_step(hd, s, h, code);
        sh[tid] = h; sc[tid] = code;
    }
    if (tid < NCHUNK) shK[tid] = g_sum_K[tid];

    // a = 1/sum(dens): deterministic block reduction (identical in every block)
    float v = g_R[tid];
    #pragma unroll
    for (int o = 16; o; o >>= 1) v += __shfl_xor_sync(0xffffffffu, v, o);
    if (ln == 0) wsum[w] = v;
    __syncthreads();
    if (w == 0) {
        float t = (ln < 8) ? wsum[ln] : 0.0f;
        #pragma unroll
        for (int o = 4; o; o >>= 1) t += __shfl_xor_sync(0xffffffffu, t, o);
        if (ln == 0) sa = 1.0f / t;
    }

    // entry state: <=9 group transforms + <=15 chunk transforms (all loads independent)
    int c = -1;
    {
        int g0 = k / GSZ;
        #pragma unroll 4
        for (int gg = 0; gg < g0; gg++) {
            int R = g_grp_r[gg * NROW + tid];
            int K = g_grp_K[gg];
            c = (R != RINF) ? R : min(c, K);
        }
        #pragma unroll 4
        for (int kk = g0 * GSZ; kk < k; kk++) {
            int r = g_sum_r[kk * NROW + tid];
            c = (r != RINF) ? r : min(c, shK[kk]);
        }
    }
    __syncthreads();   // sh/sc/sa ready

    // wait for bulk copy completion (acquire)
    {
        asm volatile(
            "{\n\t.reg .pred p;\n"
            "WAITLP_%=:\n\t"
            "mbarrier.try_wait.parity.acquire.cta.shared::cta.b64 p, [%0], 0, 0x989680;\n\t"
            "@p bra.uni WAITDN_%=;\n\t"
            "bra.uni WAITLP_%=;\n"
            "WAITDN_%=:\n\t}"
            :: "r"(mb) : "memory");
    }
    float a = sa;

    // replay: each thread owns row i, writes gi per step into mat (no syncs)
    int i = tid;
    float xi = xval(i);
    int off = i * (i + 3) / 2;
    float gi = shG[off + 1 + c];
    #pragma unroll
    for (int l = 0; l < CLEN; l++) {
        int cd = sc[l];
        int cn = c;
        if (cd == CODE_UP) {
            if (xi < sh[l]) cn = i;
        } else if (cd != CODE_NONE) {
            cn = min(c, cd);
        }
        if (cn != c) { c = cn; gi = shG[off + 1 + c]; }
        mat[l * NROW + i] = gi;
    }
    __syncthreads();

    // barrier-free epilogue: warp w reduces steps l = w, w+8, ...
    for (int l = w; l < CLEN; l += 8) {
        int s = k * CLEN + l;
        const float* row = mat + l * NROW;
        float t = 0.0f;
        #pragma unroll
        for (int j = 0; j < 8; j++) t += row[ln + 32 * j];
        #pragma unroll
        for (int o = 16; o; o >>= 1) t += __shfl_xor_sync(0xffffffffu, t, o);
        if (ln == 0 && s >= 1 && s < S_STEPS) out[s - 1] = a * t;
    }
}

extern "C" void kernel_launch(void* const* d_in, const int* in_sizes, int n_in,
                              void* d_out, int out_size) {
    const float* hd  = (const float*)d_in[0];   // h_data (4000)
    const float* raw = (const float*)d_in[1];   // raw density (32896)
    if (n_in >= 2 && in_sizes[0] != M_STEPS) {  // defensive: match by size
        const float* t = hd; hd = raw; raw = t;
    }
    float* out = (float*)d_out;

    cudaFuncSetAttribute(kC, cudaFuncAttributeMaxDynamicSharedMemorySize, GP_BYTES);

    kA<<<NCHUNK, 256>>>(raw, hd);
    kB<<<NGRP, 256>>>();
    kC<<<NCHUNK, 256, GP_BYTES>>>(hd, out);
}

// round 5
// speedup vs baseline: 1.8737x; 1.0102x over previous
#include <cuda_runtime.h>
#include <cstdint>

#define NROW     256
#define S_STEPS  4001          // hs length (M+1)
#define M_STEPS  4000
#define NCHUNK   148
#define CLEN     28            // 148*28 = 4144 >= 4001
#define GP_SIZE  33152         // sum_i (i+2) for i in [0,255]
#define GP_BYTES (GP_SIZE * 4) // 132608 bytes
#define CODE_UP   300
#define CODE_NONE 301
#define RINF     (1<<20)

// ---- device scratch (no allocations allowed; zero-init at module load) ----
__device__ __align__(16) float g_Gp[GP_SIZE];   // packed G(i,c): row i at off=i*(i+3)/2, index off+1+c
__device__ float g_R[NROW];                     // row sums of dens
__device__ int   g_sum_r[NCHUNK * NROW];        // per-chunk transform: forced value (RINF = pass)
__device__ int   g_sum_K[NCHUNK];               // per-chunk transform: min-clamp
__device__ unsigned          g_count;           // barrier arrivals (self-resetting)
__device__ volatile unsigned g_gen;             // barrier generation (monotonic across replays)

__device__ __forceinline__ float xval(int i) {
    if (i >= 255) return 1.0f;
    if (i <= 0)   return 0.0f;
    return (float)i * (1.0f / 255.0f);
}

__device__ __forceinline__ float hnorm(const float* __restrict__ hd, int s) {
    return (s == 0) ? 1.0f : (hd[s - 1] + 1.0f) * 0.5f;
}

// classify step s: up (h>p), down (h<p, code=jmax), or none
__device__ __forceinline__ void make_step(const float* __restrict__ hd, int s,
                                          float& h, int& code) {
    h = hnorm(hd, s);
    int pi = (s == 0) ? (S_STEPS - 1) : (s - 1);
    float p = hnorm(hd, pi);
    if (h > p) {
        code = CODE_UP;
    } else if (h < p) {
        int jm = (int)(h * 255.0f);
        if (jm > 255) jm = 255;
        if (jm < 0)   jm = 0;
        while (jm < 255 && xval(jm + 1) <= h) ++jm;   // exact float semantics
        while (jm >= 0 && xval(jm) > h)      --jm;
        code = jm;                                    // jmax in [-1, 255]
    } else {
        code = CODE_NONE;
    }
}

// jax.nn.softplus = max(x,0) + log1p(exp(-|x|))
__device__ __forceinline__ float softplus_f(float x) {
    return fmaxf(x, 0.0f) + log1pf(expf(-fabsf(x)));
}

__device__ __forceinline__ uint32_t s2u(const void* p) {
    uint32_t a;
    asm("{ .reg .u64 t; cvta.to.shared.u64 t, %1; cvt.u32.u64 %0, t; }" : "=r"(a) : "l"(p));
    return a;
}

// transform compose: t_out = t2 ∘ t1  (t1 applied first)
__device__ __forceinline__ void comp(int r1, int K1, int r2, int K2, int& r, int& K) {
    r = (r2 != RINF) ? r2 : ((r1 != RINF) ? min(r1, K2) : RINF);
    K = min(K1, K2);
}

// software grid barrier — safe: 148 CTAs, 1/SM, all resident in one wave
__device__ __forceinline__ void grid_barrier() {
    __syncthreads();
    if (threadIdx.x == 0) {
        __threadfence();                       // release phase-A writes
        unsigned start = g_gen;                // read BEFORE arriving (safe: flip needs our arrival)
        unsigned old = atomicAdd(&g_count, 1u);
        if (old == NCHUNK - 1) {
            g_count = 0;                       // reset for next graph replay
            __threadfence();
            atomicAdd((unsigned*)&g_gen, 1u);
        } else {
            while (g_gen == start) __nanosleep(64);
        }
        __threadfence();                       // acquire
    }
    __syncthreads();
}

extern __shared__ float shG[];   // GP_SIZE floats (132.6 KB)

__global__ void __launch_bounds__(256, 1)
kFused(const float* __restrict__ raw, const float* __restrict__ hd,
       float* __restrict__ out) {
    int k = blockIdx.x, tid = threadIdx.x, ln = tid & 31, w = tid >> 5;
    __shared__ float sh[CLEN];
    __shared__ int   sc[CLEN];
    __shared__ float wtot[8];
    __shared__ float sa;
    __shared__ float mat[CLEN * NROW];
    __shared__ __align__(8) unsigned long long mbar;

    if (tid == 0)
        asm volatile("mbarrier.init.shared.b64 [%0], 1;" :: "r"(s2u(&mbar)) : "memory");

    // ---- step descriptors for this block's chunk (kept in smem for phase C) ----
    if (tid < CLEN) {
        int s = k * CLEN + tid;
        float h = 0.0f; int code = CODE_NONE;
        if (s < S_STEPS) make_step(hd, s, h, code);
        sh[tid] = h; sc[tid] = code;
    }

    // ---- phase A1: build G rows {k, k+148} via 256-wide block scan ----
    #pragma unroll
    for (int rr = 0; rr < 2; rr++) {
        int i = k + rr * NCHUNK;
        if (i < NROW) {
            int base = i * (i + 1) / 2;
            float v = (tid <= i) ? softplus_f(raw[base + tid]) : 0.0f;

            float s = v;
            #pragma unroll
            for (int o = 1; o < 32; o <<= 1) {
                float t = __shfl_up_sync(0xffffffffu, s, o);
                if (ln >= o) s += t;
            }
            if (ln == 31) wtot[w] = s;
            __syncthreads();
            if (w == 0) {
                float t = (ln < 8) ? wtot[ln] : 0.0f;
                #pragma unroll
                for (int o = 1; o < 8; o <<= 1) {
                    float u = __shfl_up_sync(0xffffffffu, t, o);
                    if (ln >= o) t += u;
                }
                if (ln < 8) wtot[ln] = t;
            }
            __syncthreads();
            float pre = s + ((w > 0) ? wtot[w - 1] : 0.0f);
            float R = wtot[7];

            int off = i * (i + 3) / 2;
            if (tid <= i) g_Gp[off + 1 + tid] = 2.0f * pre - R;
            if (tid == 0) { g_Gp[off] = -R; g_R[i] = R; }
            __syncthreads();   // wtot reuse
        }
    }

    // ---- phase A2: summarize this chunk (sh/sc already smem-resident) ----
    {
        float xi = xval(tid);
        int r = RINF, K = RINF;
        #pragma unroll
        for (int l = 0; l < CLEN; l++) {
            int cd = sc[l];
            if (cd == CODE_UP) {
                if (xi < sh[l]) r = tid;
            } else if (cd != CODE_NONE) {
                if (r != RINF) r = min(r, cd);
                K = min(K, cd);
            }
        }
        g_sum_r[k * NROW + tid] = r;
        if (tid == 0) g_sum_K[k] = K;
    }

    // ---- grid barrier: all G rows + summaries visible ----
    grid_barrier();

    // ---- kick 132 KB bulk G copy into shared (overlapped with compose below) ----
    uint32_t mb = s2u(&mbar);
    if (tid == 0) {
        asm volatile("fence.proxy.async;" ::: "memory");
        asm volatile("mbarrier.arrive.expect_tx.shared.b64 _, [%0], %1;"
                     :: "r"(mb), "r"((uint32_t)GP_BYTES) : "memory");
        asm volatile("cp.async.bulk.shared::cluster.global.mbarrier::complete_tx::bytes "
                     "[%0], [%1], %2, [%3];"
                     :: "r"(s2u(shG)), "l"((const void*)g_Gp),
                        "r"((uint32_t)GP_BYTES), "r"(mb) : "memory");
    }

    // ---- a = 1/sum(dens): deterministic reduction (identical in every block) ----
    {
        float v = g_R[tid];
        #pragma unroll
        for (int o = 16; o; o >>= 1) v += __shfl_xor_sync(0xffffffffu, v, o);
        if (ln == 0) wtot[w] = v;
        __syncthreads();
        if (w == 0) {
            float t = (ln < 8) ? wtot[ln] : 0.0f;
            #pragma unroll
            for (int o = 4; o; o >>= 1) t += __shfl_xor_sync(0xffffffffu, t, o);
            if (ln == 0) sa = 1.0f / t;
        }
    }

    // ---- entry state: tree-compose this row's k preceding chunk transforms ----
    int c = -1;
    {
        const int* rr = g_sum_r + tid;
        int kk = 0;
        for (; kk + 8 <= k; kk += 8) {
            int r0 = rr[(kk + 0) * NROW], r1 = rr[(kk + 1) * NROW];
            int r2 = rr[(kk + 2) * NROW], r3 = rr[(kk + 3) * NROW];
            int r4 = rr[(kk + 4) * NROW], r5 = rr[(kk + 5) * NROW];
            int r6 = rr[(kk + 6) * NROW], r7 = rr[(kk + 7) * NROW];
            int K0 = __ldg(g_sum_K + kk + 0), K1 = __ldg(g_sum_K + kk + 1);
            int K2 = __ldg(g_sum_K + kk + 2), K3 = __ldg(g_sum_K + kk + 3);
            int K4 = __ldg(g_sum_K + kk + 4), K5 = __ldg(g_sum_K + kk + 5);
            int K6 = __ldg(g_sum_K + kk + 6), K7 = __ldg(g_sum_K + kk + 7);
            int ra, Ka, rb, Kb, rc2, Kc2, rd, Kd, re, Ke, rf, Kf, rg, Kg;
            comp(r0, K0, r1, K1, ra, Ka);      // depth-1 (4 independent)
            comp(r2, K2, r3, K3, rb, Kb);
            comp(r4, K4, r5, K5, rc2, Kc2);
            comp(r6, K6, r7, K7, rd, Kd);
            comp(ra, Ka, rb, Kb, re, Ke);      // depth-2 (2 independent)
            comp(rc2, Kc2, rd, Kd, rf, Kf);
            comp(re, Ke, rf, Kf, rg, Kg);      // depth-3
            c = (rg != RINF) ? rg : min(c, Kg);
        }
        for (; kk < k; kk++) {
            int r0 = rr[kk * NROW];
            int K0 = __ldg(g_sum_K + kk);
            c = (r0 != RINF) ? r0 : min(c, K0);
        }
    }
    __syncthreads();   // sa ready

    // ---- wait for bulk copy completion (acquire) ----
    asm volatile(
        "{\n\t.reg .pred p;\n"
        "WAITLP_%=:\n\t"
        "mbarrier.try_wait.parity.acquire.cta.shared::cta.b64 p, [%0], 0, 0x989680;\n\t"
        "@p bra.uni WAITDN_%=;\n\t"
        "bra.uni WAITLP_%=;\n"
        "WAITDN_%=:\n\t}"
        :: "r"(mb) : "memory");
    float a = sa;

    // ---- phase C: replay (no barriers inside the loop) ----
    int i = tid;
    float xi = xval(i);
    int off = i * (i + 3) / 2;
    float gi = shG[off + 1 + c];
    #pragma unroll
    for (int l = 0; l < CLEN; l++) {
        int cd = sc[l];
        int cn = c;
        if (cd == CODE_UP) {
            if (xi < sh[l]) cn = i;
        } else if (cd != CODE_NONE) {
            cn = min(c, cd);
        }
        if (cn != c) { c = cn; gi = shG[off + 1 + c]; }
        mat[l * NROW + i] = gi;
    }
    __syncthreads();

    // ---- barrier-free epilogue: warp w reduces steps l = w, w+8, ... ----
    for (int l = w; l < CLEN; l += 8) {
        int s = k * CLEN + l;
        const float* row = mat + l * NROW;
        float t = 0.0f;
        #pragma unroll
        for (int j = 0; j < 8; j++) t += row[ln + 32 * j];
        #pragma unroll
        for (int o = 16; o; o >>= 1) t += __shfl_xor_sync(0xffffffffu, t, o);
        if (ln == 0 && s >= 1 && s < S_STEPS) out[s - 1] = a * t;
    }
}

extern "C" void kernel_launch(void* const* d_in, const int* in_sizes, int n_in,
                              void* d_out, int out_size) {
    const float* hd  = (const float*)d_in[0];   // h_data (4000)
    const float* raw = (const float*)d_in[1];   // raw density (32896)
    if (n_in >= 2 && in_sizes[0] != M_STEPS) {  // defensive: match by size
        const float* t = hd; hd = raw; raw = t;
    }
    float* out = (float*)d_out;

    cudaFuncSetAttribute(kFused, cudaFuncAttributeMaxDynamicSharedMemorySize, GP_BYTES);

    kFused<<<NCHUNK, 256, GP_BYTES>>>(raw, hd, out);
}

// round 7
// speedup vs baseline: 2.0717x; 1.1057x over previous
#include <cuda_runtime.h>
#include <cstdint>

#define NROW     256
#define S_STEPS  4001
#define M_STEPS  4000
#define NCHUNK   148
#define CLEN     28
#define GP_SIZE  33152
#define GP_BYTES (GP_SIZE * 4)
#define CODE_UP   300
#define CODE_NONE 301
#define RINF     (1<<20)
#define NTHR     512

__device__ __align__(16) float g_Gp[GP_SIZE];
__device__ float g_R[NROW];
__device__ int   g_sum_r[NCHUNK * NROW];
__device__ int   g_sum_K[NCHUNK];
__device__ unsigned          g_count;
__device__ volatile unsigned g_gen;

__device__ __forceinline__ float xval(int i) {
    if (i >= 255) return 1.0f;
    if (i <= 0)   return 0.0f;
    return (float)i * (1.0f / 255.0f);
}

__device__ __forceinline__ float hnorm(const float* __restrict__ hd, int s) {
    return (s == 0) ? 1.0f : (hd[s - 1] + 1.0f) * 0.5f;
}

__device__ __forceinline__ void make_step(const float* __restrict__ hd, int s,
                                          float& h, int& code) {
    h = hnorm(hd, s);
    int pi = (s == 0) ? (S_STEPS - 1) : (s - 1);
    float p = hnorm(hd, pi);
    if (h > p) {
        code = CODE_UP;
    } else if (h < p) {
        int jm = (int)(h * 255.0f);
        if (jm > 255) jm = 255;
        if (jm < 0)   jm = 0;
        while (jm < 255 && xval(jm + 1) <= h) ++jm;
        while (jm >= 0 && xval(jm) > h)      --jm;
        code = jm;
    } else {
        code = CODE_NONE;
    }
}

__device__ __forceinline__ float softplus_f(float x) {
    return fmaxf(x, 0.0f) + log1pf(expf(-fabsf(x)));
}

__device__ __forceinline__ uint32_t s2u(const void* p) {
    uint32_t a;
    asm("{ .reg .u64 t; cvta.to.shared.u64 t, %1; cvt.u32.u64 %0, t; }" : "=r"(a) : "l"(p));
    return a;
}

__device__ __forceinline__ void comp(int r1, int K1, int r2, int K2, int& r, int& K) {
    r = (r2 != RINF) ? r2 : ((r1 != RINF) ? min(r1, K2) : RINF);
    K = min(K1, K2);
}

__device__ __forceinline__ void grid_barrier() {
    __syncthreads();
    if (threadIdx.x == 0) {
        __threadfence();
        unsigned start = g_gen;
        unsigned old = atomicAdd(&g_count, 1u);
        if (old == NCHUNK - 1) {
            g_count = 0;
            __threadfence();
            atomicAdd((unsigned*)&g_gen, 1u);
        } else {
            while (g_gen == start) __nanosleep(64);
        }
        __threadfence();
    }
    __syncthreads();
}

extern __shared__ float shG[];   // GP_SIZE floats (132.6 KB)

__global__ void __launch_bounds__(NTHR, 1)
kFused(const float* __restrict__ raw, const float* __restrict__ hd,
       float* __restrict__ out) {
    int k = blockIdx.x, tid = threadIdx.x;
    int half = tid >> 8;
    int t8   = tid & 255;
    int lnl  = t8 & 31;
    int wl   = t8 >> 5;
    int w    = tid >> 5;
    int ln   = tid & 31;

    __shared__ float sh[CLEN];
    __shared__ int   sc[CLEN];
    __shared__ float wtot[16];
    __shared__ float sa;
    __shared__ int   sR[NROW], sKm[NROW];   // upper half's transform
    __shared__ int   sC[NROW];              // combined entry state
    __shared__ float mat[CLEN * NROW];
    __shared__ __align__(8) unsigned long long mbar;

    if (tid == 0)
        asm volatile("mbarrier.init.shared.b64 [%0], 1;" :: "r"(s2u(&mbar)) : "memory");

    // step descriptors
    if (tid < CLEN) {
        int s = k * CLEN + tid;
        float h = 0.0f; int code = CODE_NONE;
        if (s < S_STEPS) make_step(hd, s, h, code);
        sh[tid] = h; sc[tid] = code;
    }

    // ---- phase A1: both G rows concurrently (one per 256-thread half) ----
    {
        int i = k + half * NCHUNK;
        bool valid = (i < NROW);
        float v = 0.0f;
        if (valid && t8 <= i) v = softplus_f(raw[i * (i + 1) / 2 + t8]);

        float s = v;
        #pragma unroll
        for (int o = 1; o < 32; o <<= 1) {
            float t = __shfl_up_sync(0xffffffffu, s, o);
            if (lnl >= o) s += t;
        }
        if (lnl == 31) wtot[half * 8 + wl] = s;
        __syncthreads();
        if (wl == 0) {
            float t = (lnl < 8) ? wtot[half * 8 + lnl] : 0.0f;
            #pragma unroll
            for (int o = 1; o < 8; o <<= 1) {
                float u = __shfl_up_sync(0xffffffffu, t, o);
                if (lnl >= o) t += u;
            }
            if (lnl < 8) wtot[half * 8 + lnl] = t;
        }
        __syncthreads();
        float pre = s + ((wl > 0) ? wtot[half * 8 + wl - 1] : 0.0f);
        float R = wtot[half * 8 + 7];

        if (valid) {
            int off = i * (i + 3) / 2;
            if (t8 <= i) g_Gp[off + 1 + t8] = 2.0f * pre - R;
            if (t8 == 0) { g_Gp[off] = -R; g_R[i] = R; }
        }
    }

    // ---- phase A2: chunk summary (lower half) ----
    if (half == 0) {
        float xi = xval(t8);
        int r = RINF, K = RINF;
        #pragma unroll
        for (int l = 0; l < CLEN; l++) {
            int cd = sc[l];
            if (cd == CODE_UP) {
                if (xi < sh[l]) r = t8;
            } else if (cd != CODE_NONE) {
                if (r != RINF) r = min(r, cd);
                K = min(K, cd);
            }
        }
        g_sum_r[k * NROW + t8] = r;
        if (t8 == 0) g_sum_K[k] = K;
    }

    grid_barrier();

    // ---- kick 132 KB bulk G copy into shared ----
    uint32_t mb = s2u(&mbar);
    if (tid == 0) {
        asm volatile("fence.proxy.async;" ::: "memory");
        asm volatile("mbarrier.arrive.expect_tx.shared.b64 _, [%0], %1;"
                     :: "r"(mb), "r"((uint32_t)GP_BYTES) : "memory");
        asm volatile("cp.async.bulk.shared::cluster.global.mbarrier::complete_tx::bytes "
                     "[%0], [%1], %2, [%3];"
                     :: "r"(s2u(shG)), "l"((const void*)g_Gp),
                        "r"((uint32_t)GP_BYTES), "r"(mb) : "memory");
    }

    // ---- a = 1/sum(dens): deterministic reduction (lower half) ----
    if (half == 0) {
        float v = g_R[t8];
        #pragma unroll
        for (int o = 16; o; o >>= 1) v += __shfl_xor_sync(0xffffffffu, v, o);
        if (lnl == 0) wtot[wl] = v;
    }
    __syncthreads();
    if (w == 0) {
        float t = (ln < 8) ? wtot[ln] : 0.0f;
        #pragma unroll
        for (int o = 4; o; o >>= 1) t += __shfl_xor_sync(0xffffffffu, t, o);
        if (ln == 0) sa = 1.0f / t;
    }

    // ---- compose split: lower composes [0,kmid), upper [kmid,k) ----
    {
        int kmid = k >> 1;
        int lo = half ? kmid : 0;
        int hi = half ? k : kmid;

        int R = RINF, Kc = RINF;
        const int* rr = g_sum_r + t8;
        int kk = lo;
        for (; kk + 8 <= hi; kk += 8) {
            int r0 = rr[(kk + 0) * NROW], r1 = rr[(kk + 1) * NROW];
            int r2 = rr[(kk + 2) * NROW], r3 = rr[(kk + 3) * NROW];
            int r4 = rr[(kk + 4) * NROW], r5 = rr[(kk + 5) * NROW];
            int r6 = rr[(kk + 6) * NROW], r7 = rr[(kk + 7) * NROW];
            int K0 = __ldg(g_sum_K + kk + 0), K1 = __ldg(g_sum_K + kk + 1);
            int K2 = __ldg(g_sum_K + kk + 2), K3 = __ldg(g_sum_K + kk + 3);
            int K4 = __ldg(g_sum_K + kk + 4), K5 = __ldg(g_sum_K + kk + 5);
            int K6 = __ldg(g_sum_K + kk + 6), K7 = __ldg(g_sum_K + kk + 7);
            int ra, Ka, rb, Kb, rc2, Kc2, rd, Kd, re, Ke, rf, Kf, rg, Kg;
            comp(r0, K0, r1, K1, ra, Ka);
            comp(r2, K2, r3, K3, rb, Kb);
            comp(r4, K4, r5, K5, rc2, Kc2);
            comp(r6, K6, r7, K7, rd, Kd);
            comp(ra, Ka, rb, Kb, re, Ke);
            comp(rc2, Kc2, rd, Kd, rf, Kf);
            comp(re, Ke, rf, Kf, rg, Kg);
            comp(R, Kc, rg, Kg, R, Kc);
        }
        for (; kk < hi; kk++) {
            comp(R, Kc, rr[kk * NROW], __ldg(g_sum_K + kk), R, Kc);
        }
        if (half == 1) { sR[t8] = R; sKm[t8] = Kc; }
        __syncthreads();
        if (half == 0) {
            int c = -1;
            c = (R != RINF) ? R : min(c, Kc);       // apply [0,kmid)
            int Rh = sR[t8], Kh = sKm[t8];
            c = (Rh != RINF) ? Rh : min(c, Kh);     // apply [kmid,k)
            sC[t8] = c;
        }
        __syncthreads();
    }

    // ---- wait for bulk copy completion (acquire) ----
    asm volatile(
        "{\n\t.reg .pred p;\n"
        "WAITLP_%=:\n\t"
        "mbarrier.try_wait.parity.acquire.cta.shared::cta.b64 p, [%0], 0, 0x989680;\n\t"
        "@p bra.uni WAITDN_%=;\n\t"
        "bra.uni WAITLP_%=;\n"
        "WAITDN_%=:\n\t}"
        :: "r"(mb) : "memory");
    float a = sa;

    // ---- phase C: replay (lower half; no barriers inside loop) ----
    if (half == 0) {
        int i = t8;
        float xi = xval(i);
        int off = i * (i + 3) / 2;
        int c = sC[i];
        float gi = shG[off + 1 + c];
        #pragma unroll
        for (int l = 0; l < CLEN; l++) {
            int cd = sc[l];
            int cn = c;
            if (cd == CODE_UP) {
                if (xi < sh[l]) cn = i;
            } else if (cd != CODE_NONE) {
                cn = min(c, cd);
            }
            if (cn != c) { c = cn; gi = shG[off + 1 + c]; }
            mat[l * NROW + i] = gi;
        }
    }
    __syncthreads();

    // ---- epilogue over 16 warps: warp w reduces steps l = w, w+16 ----
    for (int l = w; l < CLEN; l += 16) {
        int s = k * CLEN + l;
        const float* row = mat + l * NROW;
        float t = 0.0f;
        #pragma unroll
        for (int j = 0; j < 8; j++) t += row[ln + 32 * j];
        #pragma unroll
        for (int o = 16; o; o >>= 1) t += __shfl_xor_sync(0xffffffffu, t, o);
        if (ln == 0 && s >= 1 && s < S_STEPS) out[s - 1] = a * t;
    }
}

extern "C" void kernel_launch(void* const* d_in, const int* in_sizes, int n_in,
                              void* d_out, int out_size) {
    const float* hd  = (const float*)d_in[0];
    const float* raw = (const float*)d_in[1];
    if (n_in >= 2 && in_sizes[0] != M_STEPS) {
        const float* t = hd; hd = raw; raw = t;
    }
    float* out = (float*)d_out;

    cudaFuncSetAttribute(kFused, cudaFuncAttributeMaxDynamicSharedMemorySize, GP_BYTES);

    kFused<<<NCHUNK, NTHR, GP_BYTES>>>(raw, hd, out);
}